// round 7
// baseline (speedup 1.0000x reference)
#include <cuda_runtime.h>
#include <cstdint>

// YOLO loss R6: persistent blocks, cp.async double-buffer, fine tiles.
// 64 cells/tile, 64 threads/block, 7 blocks/SM (7 independent DRAM streams/SM).
// Compute: warp 0 = even cells, warp 1 = odd cells (uniform paths, no divergence,
// conflict-free LDS at 60-float pair stride). Deterministic reduction.

#define NCELLS  (16384 * 7 * 7)    // 802816
#define TILE_C  64                 // cells per tile
#define NPAIRS  32                 // cell pairs per tile
#define THREADS 64
#define TV4     (TILE_C * 30 / 4)  // 480 float4 per tensor per tile
#define STAGE_V4 (2 * TV4)         // 960 float4 per stage (pred + tgt)
#define NTILES  (NCELLS / TILE_C)  // 12544 exact
#define GRID    1064               // 152 SMs * 7 blocks
#define SMEM_BYTES (2 * STAGE_V4 * 16)  // 30720

__device__ float    g_partial[2048];
__device__ unsigned g_count = 0;

__device__ __forceinline__ void cp_async16(void* smem_dst, const void* gmem_src) {
    unsigned saddr = (unsigned)__cvta_generic_to_shared(smem_dst);
    asm volatile("cp.async.cg.shared.global [%0], [%1], 16;\n"
                 :: "r"(saddr), "l"(gmem_src) : "memory");
}
__device__ __forceinline__ void cp_commit() {
    asm volatile("cp.async.commit_group;\n" ::: "memory");
}
template <int N>
__device__ __forceinline__ void cp_wait() {
    asm volatile("cp.async.wait_group %0;\n" :: "n"(N) : "memory");
}

__device__ __forceinline__ float iou_f(float x1, float y1, float w1, float h1,
                                       float x2, float y2, float w2, float h2) {
    float xl = fmaxf(x1 - w1 * 0.5f, x2 - w2 * 0.5f);
    float yt = fmaxf(y1 - h1 * 0.5f, y2 - h2 * 0.5f);
    float xr = fminf(x1 + w1 * 0.5f, x2 + w2 * 0.5f);
    float yb = fminf(y1 + h1 * 0.5f, y2 + h2 * 0.5f);
    bool valid = (xr >= xl) && (yb >= yt);
    float inter = (xr - xl) * (yb - yt);
    float uni = w1 * h1 + w2 * h2 - inter;
    float safe = (uni == 0.0f) ? 1.0f : uni;
    return valid ? (inter / safe) : 0.0f;
}

__device__ __forceinline__ float cell_loss(float t0, float t1, float t2, float t3, float t4,
                                           float p0, float p1, float p2, float p3, float p4,
                                           float p5, float p6, float p7, float p8, float p9,
                                           float cls) {
    float obj   = (t4 > 0.0f)  ? 1.0f : 0.0f;
    float noobj = (t4 == 0.0f) ? 1.0f : 0.0f;

    float dno = t4 - p4;
    float conf_noobj = noobj * dno * dno;

    float iou1 = iou_f(t0, t1, t2, t3, p0, p1, p2, p3);
    float iou2 = iou_f(t0, t1, t2, t3, p5, p6, p7, p8);
    float resp1 = (iou1 > iou2) ? 1.0f : 0.0f;
    float m1 = obj * resp1;
    float m2 = obj * (1.0f - resp1);

    float d1 = iou1 - p4;
    float d2 = iou2 - p9;
    float conf_obj = m1 * d1 * d1 + m2 * d2 * d2;

    float dx1 = t0 - p0, dy1 = t1 - p1;
    float dx2 = t0 - p5, dy2 = t1 - p6;
    float xy = m1 * (dx1 * dx1 + dy1 * dy1) + m2 * (dx2 * dx2 + dy2 * dy2);

    float dw1 = t2 - p2, dh1 = t3 - p3;
    float dw2 = t2 - p7, dh2 = t3 - p8;
    float wh = m1 * (dw1 * dw1 + dh1 * dh1) + m2 * (dw2 * dw2 + dh2 * dh2);

    return 5.0f * (xy + wh) + conf_obj + 0.5f * conf_noobj + obj * cls;
}

// Even cell of a pair: channels live in slots 0..7 (p: 0..2 + class 2zw,3-6,7xy).
__device__ __forceinline__ float even_cell(const float4* __restrict__ SP,
                                           const float4* __restrict__ ST) {
    float cls = 0.0f;
#pragma unroll
    for (int j = 3; j <= 6; j++) {
        float4 a = ST[j], b = SP[j];
        float d0 = a.x - b.x, d1 = a.y - b.y, d2 = a.z - b.z, d3 = a.w - b.w;
        cls += d0 * d0 + d1 * d1 + d2 * d2 + d3 * d3;
    }
    float4 P2 = SP[2], T2 = ST[2];
    { float d0 = T2.z - P2.z, d1 = T2.w - P2.w; cls += d0 * d0 + d1 * d1; }
    float4 P7 = SP[7], T7 = ST[7];
    { float d0 = T7.x - P7.x, d1 = T7.y - P7.y; cls += d0 * d0 + d1 * d1; }

    float4 P0 = SP[0], P1 = SP[1], T0 = ST[0], T1 = ST[1];
    return cell_loss(T0.x, T0.y, T0.z, T0.w, T1.x,
                     P0.x, P0.y, P0.z, P0.w, P1.x,
                     P1.y, P1.z, P1.w, P2.x, P2.y, cls);
}

// Odd cell of a pair: channels live in slots 7..14.
__device__ __forceinline__ float odd_cell(const float4* __restrict__ SP,
                                          const float4* __restrict__ ST) {
    float cls = 0.0f;
#pragma unroll
    for (int j = 10; j <= 14; j++) {
        float4 a = ST[j], b = SP[j];
        float d0 = a.x - b.x, d1 = a.y - b.y, d2 = a.z - b.z, d3 = a.w - b.w;
        cls += d0 * d0 + d1 * d1 + d2 * d2 + d3 * d3;
    }
    float4 P7 = SP[7], P8 = SP[8], P9 = SP[9];
    float4 T7 = ST[7], T8 = ST[8];
    return cell_loss(T7.z, T7.w, T8.x, T8.y, T8.z,
                     P7.z, P7.w, P8.x, P8.y, P8.z,
                     P8.w, P9.x, P9.y, P9.z, P9.w, cls);
}

__device__ __forceinline__ void prefetch_tile(float4* sbuf, int s,
                                              const float4* __restrict__ gp,
                                              const float4* __restrict__ gt,
                                              int tile, int tid) {
    float4* dst = sbuf + s * STAGE_V4;
    const float4* srcp = gp + (size_t)tile * TV4;
    const float4* srct = gt + (size_t)tile * TV4;
#pragma unroll
    for (int k = 0; k < 15; k++) {
        int i = k * THREADS + tid;               // 0..959
        const float4* src = (i < TV4) ? (srcp + i) : (srct + (i - TV4));
        cp_async16(dst + i, src);
    }
}

__global__ void __launch_bounds__(THREADS)
yolo_fused_kernel(const float* __restrict__ pred,
                  const float* __restrict__ tgt,
                  float* __restrict__ out) {
    extern __shared__ float4 sbuf[];       // 2 stages x (480 pred + 480 tgt)
    __shared__ float swarp[2];
    __shared__ int   s_isLast;

    const int tid  = threadIdx.x;
    const int lane = tid & 31;
    const int wid  = tid >> 5;             // warp 0: even cells, warp 1: odd cells
    const float4* gp = reinterpret_cast<const float4*>(pred);
    const float4* gt = reinterpret_cast<const float4*>(tgt);

    float loss = 0.0f;

    int t = blockIdx.x;
    int stage = 0;
    prefetch_tile(sbuf, 0, gp, gt, t, tid);
    cp_commit();

    while (t < NTILES) {
        int tn = t + GRID;
        if (tn < NTILES) {
            prefetch_tile(sbuf, stage ^ 1, gp, gt, tn, tid);
            cp_commit();
            cp_wait<1>();
        } else {
            cp_wait<0>();
        }
        __syncthreads();

        {
            // warp w handles the (w?odd:even) cell of pair `lane` (32 pairs/tile).
            const float4* SP = sbuf + stage * STAGE_V4 + lane * 15;
            const float4* ST = SP + TV4;
            loss += (wid == 0) ? even_cell(SP, ST) : odd_cell(SP, ST);
        }
        __syncthreads();
        stage ^= 1;
        t = tn;
    }

    // ---- block reduce (deterministic) ----
#pragma unroll
    for (int off = 16; off > 0; off >>= 1)
        loss += __shfl_down_sync(0xFFFFFFFFu, loss, off);

    if (lane == 0) swarp[wid] = loss;
    __syncthreads();

    if (tid == 0) {
        g_partial[blockIdx.x] = swarp[0] + swarp[1];
        __threadfence();
        unsigned v = atomicAdd(&g_count, 1u);
        s_isLast = (v == (unsigned)(gridDim.x - 1)) ? 1 : 0;
    }
    __syncthreads();

    // ---- last block: deterministic final reduction ----
    if (s_isLast) {
        __shared__ double sd[THREADS];
        double acc = 0.0;
        for (int i = tid; i < GRID; i += THREADS)
            acc += (double)g_partial[i];
        sd[tid] = acc;
        __syncthreads();
#pragma unroll
        for (int stride = THREADS / 2; stride > 0; stride >>= 1) {
            if (tid < stride) sd[tid] += sd[tid + stride];
            __syncthreads();
        }
        if (tid == 0) {
            out[0] = (float)(sd[0] / 16384.0);
            g_count = 0;   // reset for next graph replay
        }
    }
}

extern "C" void kernel_launch(void* const* d_in, const int* in_sizes, int n_in,
                              void* d_out, int out_size) {
    const float* y  = (const float*)d_in[0];
    const float* gt = (const float*)d_in[1];
    float* out = (float*)d_out;

    static int attr_done = 0;
    if (!attr_done) {
        cudaFuncSetAttribute(yolo_fused_kernel,
                             cudaFuncAttributeMaxDynamicSharedMemorySize, SMEM_BYTES);
        attr_done = 1;
    }

    yolo_fused_kernel<<<GRID, THREADS, SMEM_BYTES>>>(y, gt, out);
}

// round 8
// speedup vs baseline: 1.1284x; 1.1284x over previous
#include <cuda_runtime.h>
#include <cstdint>

// YOLO loss R8: persistent blocks, 3-stage cp.async ring (2 groups in flight
// per block during compute), 128 threads all active in compute via even/odd
// warp specialization over 64 pairs. Deterministic reduction.

#define NCELLS  (16384 * 7 * 7)    // 802816
#define TILE_C  128                // cells per tile
#define THREADS 128
#define TV4     (TILE_C * 30 / 4)  // 960 float4 per tensor per tile
#define STAGE_V4 (2 * TV4)         // 1920 float4 per stage (pred + tgt)
#define NSTAGES 3
#define NTILES  (NCELLS / TILE_C)  // 6272 exact
#define GRID    304                // 152 SMs * 2 blocks
#define SMEM_BYTES (NSTAGES * STAGE_V4 * 16)  // 92160

__device__ float    g_partial[2048];
__device__ unsigned g_count = 0;

__device__ __forceinline__ void cp_async16(void* smem_dst, const void* gmem_src) {
    unsigned saddr = (unsigned)__cvta_generic_to_shared(smem_dst);
    asm volatile("cp.async.cg.shared.global [%0], [%1], 16;\n"
                 :: "r"(saddr), "l"(gmem_src) : "memory");
}
__device__ __forceinline__ void cp_commit() {
    asm volatile("cp.async.commit_group;\n" ::: "memory");
}
template <int N>
__device__ __forceinline__ void cp_wait() {
    asm volatile("cp.async.wait_group %0;\n" :: "n"(N) : "memory");
}

__device__ __forceinline__ float iou_f(float x1, float y1, float w1, float h1,
                                       float x2, float y2, float w2, float h2) {
    float xl = fmaxf(x1 - w1 * 0.5f, x2 - w2 * 0.5f);
    float yt = fmaxf(y1 - h1 * 0.5f, y2 - h2 * 0.5f);
    float xr = fminf(x1 + w1 * 0.5f, x2 + w2 * 0.5f);
    float yb = fminf(y1 + h1 * 0.5f, y2 + h2 * 0.5f);
    bool valid = (xr >= xl) && (yb >= yt);
    float inter = (xr - xl) * (yb - yt);
    float uni = w1 * h1 + w2 * h2 - inter;
    float safe = (uni == 0.0f) ? 1.0f : uni;
    return valid ? (inter / safe) : 0.0f;
}

__device__ __forceinline__ float cell_loss(float t0, float t1, float t2, float t3, float t4,
                                           float p0, float p1, float p2, float p3, float p4,
                                           float p5, float p6, float p7, float p8, float p9,
                                           float cls) {
    float obj   = (t4 > 0.0f)  ? 1.0f : 0.0f;
    float noobj = (t4 == 0.0f) ? 1.0f : 0.0f;

    float dno = t4 - p4;
    float conf_noobj = noobj * dno * dno;

    float iou1 = iou_f(t0, t1, t2, t3, p0, p1, p2, p3);
    float iou2 = iou_f(t0, t1, t2, t3, p5, p6, p7, p8);
    float resp1 = (iou1 > iou2) ? 1.0f : 0.0f;
    float m1 = obj * resp1;
    float m2 = obj * (1.0f - resp1);

    float d1 = iou1 - p4;
    float d2 = iou2 - p9;
    float conf_obj = m1 * d1 * d1 + m2 * d2 * d2;

    float dx1 = t0 - p0, dy1 = t1 - p1;
    float dx2 = t0 - p5, dy2 = t1 - p6;
    float xy = m1 * (dx1 * dx1 + dy1 * dy1) + m2 * (dx2 * dx2 + dy2 * dy2);

    float dw1 = t2 - p2, dh1 = t3 - p3;
    float dw2 = t2 - p7, dh2 = t3 - p8;
    float wh = m1 * (dw1 * dw1 + dh1 * dh1) + m2 * (dw2 * dw2 + dh2 * dh2);

    return 5.0f * (xy + wh) + conf_obj + 0.5f * conf_noobj + obj * cls;
}

// Even cell of a pair (slots 0..7): static mapping.
__device__ __forceinline__ float even_cell(const float4* __restrict__ SP,
                                           const float4* __restrict__ ST) {
    float cls = 0.0f;
#pragma unroll
    for (int j = 3; j <= 6; j++) {
        float4 a = ST[j], b = SP[j];
        float d0 = a.x - b.x, d1 = a.y - b.y, d2 = a.z - b.z, d3 = a.w - b.w;
        cls += d0 * d0 + d1 * d1 + d2 * d2 + d3 * d3;
    }
    float4 P2 = SP[2], T2 = ST[2];
    { float d0 = T2.z - P2.z, d1 = T2.w - P2.w; cls += d0 * d0 + d1 * d1; }
    float4 P7 = SP[7], T7 = ST[7];
    { float d0 = T7.x - P7.x, d1 = T7.y - P7.y; cls += d0 * d0 + d1 * d1; }

    float4 P0 = SP[0], P1 = SP[1], T0 = ST[0], T1 = ST[1];
    return cell_loss(T0.x, T0.y, T0.z, T0.w, T1.x,
                     P0.x, P0.y, P0.z, P0.w, P1.x,
                     P1.y, P1.z, P1.w, P2.x, P2.y, cls);
}

// Odd cell of a pair (slots 7..14): static mapping.
__device__ __forceinline__ float odd_cell(const float4* __restrict__ SP,
                                          const float4* __restrict__ ST) {
    float cls = 0.0f;
#pragma unroll
    for (int j = 10; j <= 14; j++) {
        float4 a = ST[j], b = SP[j];
        float d0 = a.x - b.x, d1 = a.y - b.y, d2 = a.z - b.z, d3 = a.w - b.w;
        cls += d0 * d0 + d1 * d1 + d2 * d2 + d3 * d3;
    }
    float4 P7 = SP[7], P8 = SP[8], P9 = SP[9];
    float4 T7 = ST[7], T8 = ST[8];
    return cell_loss(T7.z, T7.w, T8.x, T8.y, T8.z,
                     P7.z, P7.w, P8.x, P8.y, P8.z,
                     P8.w, P9.x, P9.y, P9.z, P9.w, cls);
}

__device__ __forceinline__ void prefetch_tile(float4* sbuf, int s,
                                              const float4* __restrict__ gp,
                                              const float4* __restrict__ gt,
                                              int tile, int tid) {
    float4* dst = sbuf + s * STAGE_V4;
    const float4* srcp = gp + (size_t)tile * TV4;
    const float4* srct = gt + (size_t)tile * TV4;
#pragma unroll
    for (int k = 0; k < 15; k++) {
        int i = k * THREADS + tid;               // 0..1919
        const float4* src = (i < TV4) ? (srcp + i) : (srct + (i - TV4));
        cp_async16(dst + i, src);
    }
}

__global__ void __launch_bounds__(THREADS)
yolo_fused_kernel(const float* __restrict__ pred,
                  const float* __restrict__ tgt,
                  float* __restrict__ out) {
    extern __shared__ float4 sbuf[];       // 3 stages x (960 pred + 960 tgt)
    __shared__ float swarp[THREADS / 32];
    __shared__ int   s_isLast;

    const int tid  = threadIdx.x;
    const int lane = tid & 31;
    const int wid  = tid >> 5;
    const float4* gp = reinterpret_cast<const float4*>(pred);
    const float4* gt = reinterpret_cast<const float4*>(tgt);

    float loss = 0.0f;

    int t = blockIdx.x;
    int stage = 0;

    if (t < NTILES)        prefetch_tile(sbuf, 0, gp, gt, t, tid);
    cp_commit();
    if (t + GRID < NTILES) prefetch_tile(sbuf, 1, gp, gt, t + GRID, tid);
    cp_commit();

    while (t < NTILES) {
        int t2 = t + 2 * GRID;
        if (t2 < NTILES) {
            prefetch_tile(sbuf, (stage + 2) % NSTAGES, gp, gt, t2, tid);
            cp_commit();
            cp_wait<2>();            // current tile's group has landed
        } else if (t + GRID < NTILES) {
            cp_commit();             // empty group keeps the count aligned
            cp_wait<2>();
        } else {
            cp_wait<0>();
        }
        __syncthreads();

        {
            // warp w: (w&1 ? odd : even) cell of pair (w>>1)*32 + lane.
            int pair = ((wid >> 1) << 5) + lane;
            const float4* SP = sbuf + stage * STAGE_V4 + pair * 15;
            const float4* ST = SP + TV4;
            loss += (wid & 1) ? odd_cell(SP, ST) : even_cell(SP, ST);
        }
        __syncthreads();             // all reads done before this stage is refilled
        stage = (stage + 1) % NSTAGES;
        t += GRID;
    }

    // ---- block reduce (deterministic) ----
#pragma unroll
    for (int off = 16; off > 0; off >>= 1)
        loss += __shfl_down_sync(0xFFFFFFFFu, loss, off);

    if (lane == 0) swarp[wid] = loss;
    __syncthreads();

    if (tid == 0) {
        g_partial[blockIdx.x] = swarp[0] + swarp[1] + swarp[2] + swarp[3];
        __threadfence();
        unsigned v = atomicAdd(&g_count, 1u);
        s_isLast = (v == (unsigned)(gridDim.x - 1)) ? 1 : 0;
    }
    __syncthreads();

    // ---- last block: deterministic final reduction ----
    if (s_isLast) {
        __shared__ double sd[THREADS];
        double acc = 0.0;
        for (int i = tid; i < GRID; i += THREADS)
            acc += (double)g_partial[i];
        sd[tid] = acc;
        __syncthreads();
#pragma unroll
        for (int stride = THREADS / 2; stride > 0; stride >>= 1) {
            if (tid < stride) sd[tid] += sd[tid + stride];
            __syncthreads();
        }
        if (tid == 0) {
            out[0] = (float)(sd[0] / 16384.0);
            g_count = 0;   // reset for next graph replay
        }
    }
}

extern "C" void kernel_launch(void* const* d_in, const int* in_sizes, int n_in,
                              void* d_out, int out_size) {
    const float* y  = (const float*)d_in[0];
    const float* gt = (const float*)d_in[1];
    float* out = (float*)d_out;

    static int attr_done = 0;
    if (!attr_done) {
        cudaFuncSetAttribute(yolo_fused_kernel,
                             cudaFuncAttributeMaxDynamicSharedMemorySize, SMEM_BYTES);
        attr_done = 1;
    }

    yolo_fused_kernel<<<GRID, THREADS, SMEM_BYTES>>>(y, gt, out);
}

// round 9
// speedup vs baseline: 1.1489x; 1.0182x over previous
#include <cuda_runtime.h>
#include <cstdint>

// YOLO loss R9: persistent blocks + TMA (cp.async.bulk) mbarrier ring.
// No block-wide syncs in the main loop: producer (tid 0) refills a stage as
// soon as its empty barrier flips; consumer warps spin on per-stage full
// parity and arrive on empty when done. 3-stage ring x 60KB, 1 block/SM.
// Compute: static even/odd pair mapping (R4). Deterministic reduction.

#define NCELLS  (16384 * 7 * 7)     // 802816
#define TILE_C  256                 // cells per tile
#define NPAIRS  128                 // pairs per tile
#define THREADS 256
#define TV4     (TILE_C * 30 / 4)   // 1920 float4 per tensor per tile
#define STAGE_V4 (2 * TV4)          // 3840 float4 per stage
#define TENSOR_BYTES (TV4 * 16)     // 30720
#define STAGE_BYTES  (STAGE_V4 * 16)// 61440
#define NSTAGES 3
#define NTILES  (NCELLS / TILE_C)   // 3136 exact
#define GRID    152                 // 1 block per SM
#define SMEM_BYTES (NSTAGES * STAGE_BYTES)  // 184320

__device__ float    g_partial[1024];
__device__ unsigned g_count = 0;

// ---------- PTX helpers ----------
__device__ __forceinline__ uint32_t smem_u32(const void* p) {
    return (uint32_t)__cvta_generic_to_shared(p);
}
__device__ __forceinline__ void mbar_init(uint32_t mbar, uint32_t count) {
    asm volatile("mbarrier.init.shared.b64 [%0], %1;" :: "r"(mbar), "r"(count) : "memory");
}
__device__ __forceinline__ void mbar_arrive(uint32_t mbar) {
    asm volatile("mbarrier.arrive.shared.b64 _, [%0];" :: "r"(mbar) : "memory");
}
__device__ __forceinline__ void mbar_expect_tx(uint32_t mbar, uint32_t bytes) {
    asm volatile("mbarrier.arrive.expect_tx.shared.b64 _, [%0], %1;"
                 :: "r"(mbar), "r"(bytes) : "memory");
}
__device__ __forceinline__ void mbar_wait(uint32_t mbar, uint32_t phase) {
    asm volatile(
        "{\n\t.reg .pred P;\n\t"
        "WAIT_%=:\n\t"
        "mbarrier.try_wait.parity.acquire.cta.shared::cta.b64 P, [%0], %1, 0x989680;\n\t"
        "@P bra.uni DONE_%=;\n\t"
        "bra.uni WAIT_%=;\n\t"
        "DONE_%=:\n\t}"
        :: "r"(mbar), "r"(phase) : "memory");
}
__device__ __forceinline__ void tma_bulk_g2s(uint32_t dst, const void* src,
                                             uint32_t bytes, uint32_t mbar) {
    asm volatile("cp.async.bulk.shared::cta.global.mbarrier::complete_tx::bytes "
                 "[%0], [%1], %2, [%3];"
                 :: "r"(dst), "l"(src), "r"(bytes), "r"(mbar) : "memory");
}
__device__ __forceinline__ void fence_async_shared() {
    asm volatile("fence.proxy.async.shared::cta;" ::: "memory");
}

// ---------- math ----------
__device__ __forceinline__ float iou_f(float x1, float y1, float w1, float h1,
                                       float x2, float y2, float w2, float h2) {
    float xl = fmaxf(x1 - w1 * 0.5f, x2 - w2 * 0.5f);
    float yt = fmaxf(y1 - h1 * 0.5f, y2 - h2 * 0.5f);
    float xr = fminf(x1 + w1 * 0.5f, x2 + w2 * 0.5f);
    float yb = fminf(y1 + h1 * 0.5f, y2 + h2 * 0.5f);
    bool valid = (xr >= xl) && (yb >= yt);
    float inter = (xr - xl) * (yb - yt);
    float uni = w1 * h1 + w2 * h2 - inter;
    float safe = (uni == 0.0f) ? 1.0f : uni;
    return valid ? (inter / safe) : 0.0f;
}

__device__ __forceinline__ float cell_loss(float t0, float t1, float t2, float t3, float t4,
                                           float p0, float p1, float p2, float p3, float p4,
                                           float p5, float p6, float p7, float p8, float p9,
                                           float cls) {
    float obj   = (t4 > 0.0f)  ? 1.0f : 0.0f;
    float noobj = (t4 == 0.0f) ? 1.0f : 0.0f;

    float dno = t4 - p4;
    float conf_noobj = noobj * dno * dno;

    float iou1 = iou_f(t0, t1, t2, t3, p0, p1, p2, p3);
    float iou2 = iou_f(t0, t1, t2, t3, p5, p6, p7, p8);
    float resp1 = (iou1 > iou2) ? 1.0f : 0.0f;
    float m1 = obj * resp1;
    float m2 = obj * (1.0f - resp1);

    float d1 = iou1 - p4;
    float d2 = iou2 - p9;
    float conf_obj = m1 * d1 * d1 + m2 * d2 * d2;

    float dx1 = t0 - p0, dy1 = t1 - p1;
    float dx2 = t0 - p5, dy2 = t1 - p6;
    float xy = m1 * (dx1 * dx1 + dy1 * dy1) + m2 * (dx2 * dx2 + dy2 * dy2);

    float dw1 = t2 - p2, dh1 = t3 - p3;
    float dw2 = t2 - p7, dh2 = t3 - p8;
    float wh = m1 * (dw1 * dw1 + dh1 * dh1) + m2 * (dw2 * dw2 + dh2 * dh2);

    return 5.0f * (xy + wh) + conf_obj + 0.5f * conf_noobj + obj * cls;
}

// Even cell of a pair (slots 0..7): static mapping.
__device__ __forceinline__ float even_cell(const float4* __restrict__ SP,
                                           const float4* __restrict__ ST) {
    float cls = 0.0f;
#pragma unroll
    for (int j = 3; j <= 6; j++) {
        float4 a = ST[j], b = SP[j];
        float d0 = a.x - b.x, d1 = a.y - b.y, d2 = a.z - b.z, d3 = a.w - b.w;
        cls += d0 * d0 + d1 * d1 + d2 * d2 + d3 * d3;
    }
    float4 P2 = SP[2], T2 = ST[2];
    { float d0 = T2.z - P2.z, d1 = T2.w - P2.w; cls += d0 * d0 + d1 * d1; }
    float4 P7 = SP[7], T7 = ST[7];
    { float d0 = T7.x - P7.x, d1 = T7.y - P7.y; cls += d0 * d0 + d1 * d1; }

    float4 P0 = SP[0], P1 = SP[1], T0 = ST[0], T1 = ST[1];
    return cell_loss(T0.x, T0.y, T0.z, T0.w, T1.x,
                     P0.x, P0.y, P0.z, P0.w, P1.x,
                     P1.y, P1.z, P1.w, P2.x, P2.y, cls);
}

// Odd cell of a pair (slots 7..14): static mapping.
__device__ __forceinline__ float odd_cell(const float4* __restrict__ SP,
                                          const float4* __restrict__ ST) {
    float cls = 0.0f;
#pragma unroll
    for (int j = 10; j <= 14; j++) {
        float4 a = ST[j], b = SP[j];
        float d0 = a.x - b.x, d1 = a.y - b.y, d2 = a.z - b.z, d3 = a.w - b.w;
        cls += d0 * d0 + d1 * d1 + d2 * d2 + d3 * d3;
    }
    float4 P7 = SP[7], P8 = SP[8], P9 = SP[9];
    float4 T7 = ST[7], T8 = ST[8];
    return cell_loss(T7.z, T7.w, T8.x, T8.y, T8.z,
                     P7.z, P7.w, P8.x, P8.y, P8.z,
                     P8.w, P9.x, P9.y, P9.z, P9.w, cls);
}

__global__ void __launch_bounds__(THREADS)
yolo_fused_kernel(const float* __restrict__ pred,
                  const float* __restrict__ tgt,
                  float* __restrict__ out) {
    extern __shared__ float4 sbuf[];            // 3 stages x 3840 float4
    __shared__ uint64_t mb_full[NSTAGES];
    __shared__ uint64_t mb_empty[NSTAGES];
    __shared__ float    swarp[THREADS / 32];
    __shared__ int      s_isLast;

    const int tid  = threadIdx.x;
    const int lane = tid & 31;
    const int wid  = tid >> 5;
    const char* gpb = reinterpret_cast<const char*>(pred);
    const char* gtb = reinterpret_cast<const char*>(tgt);

    uint32_t full_a[NSTAGES], empty_a[NSTAGES], stage_a[NSTAGES];
#pragma unroll
    for (int s = 0; s < NSTAGES; s++) {
        full_a[s]  = smem_u32(&mb_full[s]);
        empty_a[s] = smem_u32(&mb_empty[s]);
        stage_a[s] = smem_u32(sbuf + s * STAGE_V4);
    }

    if (tid == 0) {
#pragma unroll
        for (int s = 0; s < NSTAGES; s++) {
            mbar_init(full_a[s], 1);
            mbar_init(empty_a[s], THREADS);
        }
        fence_async_shared();
    }
    __syncthreads();

    // Prologue: fill all stages.
    if (tid == 0) {
#pragma unroll
        for (int s = 0; s < NSTAGES; s++) {
            long tk = (long)blockIdx.x + (long)s * GRID;
            if (tk < NTILES) {
                mbar_expect_tx(full_a[s], STAGE_BYTES);
                tma_bulk_g2s(stage_a[s], gpb + tk * TENSOR_BYTES, TENSOR_BYTES, full_a[s]);
                tma_bulk_g2s(stage_a[s] + TENSOR_BYTES, gtb + tk * TENSOR_BYTES,
                             TENSOR_BYTES, full_a[s]);
            }
        }
    }

    float loss = 0.0f;
    const int pair = ((wid >> 1) << 5) + lane;   // 0..127
    const int odd  = wid & 1;

    int s = 0;
    uint32_t ph = 0;                              // parity = (iter/NSTAGES)&1
    for (int t = blockIdx.x; t < NTILES; t += GRID) {
        // consume stage s
        mbar_wait(full_a[s], ph);
        {
            const float4* SP = reinterpret_cast<const float4*>(sbuf) +
                               (size_t)s * STAGE_V4 + pair * 15;
            const float4* ST = SP + TV4;
            loss += odd ? odd_cell(SP, ST) : even_cell(SP, ST);
        }
        mbar_arrive(empty_a[s]);

        // producer: refill this stage for tile t + 3*GRID once it drains
        if (tid == 0) {
            long tn = (long)t + (long)NSTAGES * GRID;
            if (tn < NTILES) {
                mbar_wait(empty_a[s], ph);
                fence_async_shared();
                mbar_expect_tx(full_a[s], STAGE_BYTES);
                tma_bulk_g2s(stage_a[s], gpb + tn * TENSOR_BYTES, TENSOR_BYTES, full_a[s]);
                tma_bulk_g2s(stage_a[s] + TENSOR_BYTES, gtb + tn * TENSOR_BYTES,
                             TENSOR_BYTES, full_a[s]);
            }
        }

        if (++s == NSTAGES) { s = 0; ph ^= 1; }
    }

    // ---- block reduce (deterministic) ----
#pragma unroll
    for (int off = 16; off > 0; off >>= 1)
        loss += __shfl_down_sync(0xFFFFFFFFu, loss, off);

    if (lane == 0) swarp[wid] = loss;
    __syncthreads();

    if (tid == 0) {
        float bsum = 0.0f;
#pragma unroll
        for (int w = 0; w < THREADS / 32; w++) bsum += swarp[w];
        g_partial[blockIdx.x] = bsum;
        __threadfence();
        unsigned v = atomicAdd(&g_count, 1u);
        s_isLast = (v == (unsigned)(gridDim.x - 1)) ? 1 : 0;
    }
    __syncthreads();

    // ---- last block: deterministic final reduction ----
    if (s_isLast) {
        __shared__ double sd[THREADS];
        double acc = 0.0;
        for (int i = tid; i < GRID; i += THREADS)
            acc += (double)g_partial[i];
        sd[tid] = acc;
        __syncthreads();
#pragma unroll
        for (int stride = THREADS / 2; stride > 0; stride >>= 1) {
            if (tid < stride) sd[tid] += sd[tid + stride];
            __syncthreads();
        }
        if (tid == 0) {
            out[0] = (float)(sd[0] / 16384.0);
            g_count = 0;   // reset for next graph replay
        }
    }
}

extern "C" void kernel_launch(void* const* d_in, const int* in_sizes, int n_in,
                              void* d_out, int out_size) {
    const float* y  = (const float*)d_in[0];
    const float* gt = (const float*)d_in[1];
    float* out = (float*)d_out;

    static int attr_done = 0;
    if (!attr_done) {
        cudaFuncSetAttribute(yolo_fused_kernel,
                             cudaFuncAttributeMaxDynamicSharedMemorySize, SMEM_BYTES);
        attr_done = 1;
    }

    yolo_fused_kernel<<<GRID, THREADS, SMEM_BYTES>>>(y, gt, out);
}